// round 2
// baseline (speedup 1.0000x reference)
#include <cuda_runtime.h>

typedef unsigned long long ull;

// Problem constants
constexpr int T_ = 30;
constexpr int BT = 64;     // batch elements per block
constexpr int NT = 256;    // threads per block
constexpr int NBLK = 32768 / BT;  // 512

// ---------------- SMEM layout (in floats) ----------------
// Persistent state region (shared by both phases)
constexpr int S_H2   = 0;              // 32*64   h2 / latent
constexpr int S_H1   = 2048;           // 64*64   h1 / hd1
constexpr int S_HD2  = 6144;           // 4*64    hd2
constexpr int S_XS   = 6400;           // 4*64    x staging
constexpr int S_B1   = 6656;           // 256     enc1 bias (permuted)
constexpr int S_B2   = 6912;           // 128     enc2 bias (permuted)
constexpr int S_BD2  = 7040;           // 16      dec2 bias (permuted)
constexpr int S_P2   = 7056;           // 16*64   dec2 preact staging
// Phase weight region
constexpr int S_W    = 8192;
// encode layout
constexpr int S_W1H  = S_W;            // [64][256]
constexpr int S_W1X  = S_W + 16384;    // [4][256]
constexpr int S_W2X  = S_W1X + 1024;   // [64][128]
constexpr int S_W2H  = S_W2X + 8192;   // [32][128]
// decode layout (overwrites encode)
constexpr int S_WD1H = S_W;            // [64][256]
constexpr int S_XG   = S_W + 16384;    // [256][64] const dec1 preactivation
constexpr int S_WD1X = S_XG + 16384;   // [32][256] (temp, used only for XG build)
constexpr int S_WD2X = S_WD1X + 8192;  // [64][16]
constexpr int S_WD2H = S_WD2X + 1024;  // [4][16]
constexpr int SMEM_FLOATS = S_WD2H + 64;       // 50240
constexpr int SMEM_BYTES  = SMEM_FLOATS * 4;   // 200960

// ---------------- packed f32x2 helpers ----------------
__device__ __forceinline__ ull ffma2(ull a, ull b, ull c) {
    ull d;
    asm("fma.rn.f32x2 %0, %1, %2, %3;" : "=l"(d) : "l"(a), "l"(b), "l"(c));
    return d;
}
__device__ __forceinline__ ull dup2(float x) {
    ull d; asm("mov.b64 %0, {%1, %1};" : "=l"(d) : "f"(x)); return d;
}
__device__ __forceinline__ float2 unpack2(ull v) {
    float2 f; asm("mov.b64 {%0, %1}, %2;" : "=f"(f.x), "=f"(f.y) : "l"(v)); return f;
}
__device__ __forceinline__ ull pack2(float x, float y) {
    ull v; asm("mov.b64 %0, {%1, %2};" : "=l"(v) : "f"(x), "f"(y)); return v;
}

// ---------------- activations (full fp32 accuracy ~1e-6) ----------------
__device__ __forceinline__ float sigf(float x) {
    return __fdividef(1.f, 1.f + __expf(-x));
}
__device__ __forceinline__ float tanh_f(float x) {
    float e = __expf(-2.f * fabsf(x));
    float t = __fdividef(1.f - e, 1.f + e);
    return (x >= 0.f) ? t : -t;
}
__device__ __forceinline__ void cell(float pi, float pf, float pg, float po,
                                     float &c, float &h) {
    c = sigf(pf) * c + sigf(pi) * tanh_f(pg);
    h = sigf(po) * tanh_f(c);
}

// Load weight matrix W[4*HID][K] (row-major) into smem transposed+gate-permuted:
// smem[j*(4*HID) + (4*(g%HID) + g/HID)] = W[g][j]
__device__ __forceinline__ void load_w_perm(const float* __restrict__ g,
                                            float* __restrict__ s,
                                            int HID, int K, int tid) {
    int n = 4 * HID * K;
    int FG = 4 * HID;
    for (int idx = tid; idx < n; idx += NT) {
        int gr = idx / K;
        int j = idx - gr * K;
        int gp = 4 * (gr % HID) + (gr / HID);
        s[j * FG + gp] = g[idx];
    }
}

extern __shared__ float sm[];

__global__ __launch_bounds__(NT, 1)
void lstm_ae_kernel(const float* __restrict__ x,
                    const float* __restrict__ e1_Wih, const float* __restrict__ e1_Whh,
                    const float* __restrict__ e1_bih, const float* __restrict__ e1_bhh,
                    const float* __restrict__ e2_Wih, const float* __restrict__ e2_Whh,
                    const float* __restrict__ e2_bih, const float* __restrict__ e2_bhh,
                    const float* __restrict__ d1_Wih, const float* __restrict__ d1_Whh,
                    const float* __restrict__ d1_bih, const float* __restrict__ d1_bhh,
                    const float* __restrict__ d2_Wih, const float* __restrict__ d2_Whh,
                    const float* __restrict__ d2_bih, const float* __restrict__ d2_bhh,
                    float* __restrict__ out) {
    const int tid = threadIdx.x;
    const int base = blockIdx.x * BT;

    // ---- load encode weights (transposed + gate-permuted) ----
    load_w_perm(e1_Whh, sm + S_W1H, 64, 64, tid);
    load_w_perm(e1_Wih, sm + S_W1X, 64, 4, tid);
    load_w_perm(e2_Wih, sm + S_W2X, 32, 64, tid);
    load_w_perm(e2_Whh, sm + S_W2H, 32, 32, tid);
    if (tid < 256) {
        int g = tid, gp = 4 * (g % 64) + g / 64;
        sm[S_B1 + gp] = e1_bih[g] + e1_bhh[g];
    }
    if (tid < 128) {
        int g = tid, gp = 4 * (g % 32) + g / 32;
        sm[S_B2 + gp] = e2_bih[g] + e2_bhh[g];
    }
    for (int i = tid; i < 4096; i += NT) sm[S_H1 + i] = 0.f;
    for (int i = tid; i < 2048; i += NT) sm[S_H2 + i] = 0.f;

    // thread tiles
    const int bx = tid & 7;
    const int gx = tid >> 3;          // 0..31
    const int b0 = bx * 8;            // 8 batch = 4 f32x2 pairs
    const int g0a = gx * 8;           // 256-gate layers: rows g0a..g0a+7 (k = 2gx, 2gx+1)
    const int g0b = gx * 4;           // 128-gate layer:  rows g0b..g0b+3 (k = gx)

    ull c1[2][4], c2[4];
#pragma unroll
    for (int a = 0; a < 2; a++)
#pragma unroll
        for (int p = 0; p < 4; p++) c1[a][p] = 0ull;
#pragma unroll
    for (int p = 0; p < 4; p++) c2[p] = 0ull;

    __syncthreads();

    // =================== ENCODE ===================
    for (int t = 0; t < T_; t++) {
        if (tid < BT) {
            const float4 v = reinterpret_cast<const float4*>(x)[(base + tid) * T_ + t];
            sm[S_XS + 0 * 64 + tid] = v.x;
            sm[S_XS + 1 * 64 + tid] = v.y;
            sm[S_XS + 2 * 64 + tid] = v.z;
            sm[S_XS + 3 * 64 + tid] = v.w;
        }
        __syncthreads();

        // ---- enc1 GEMM: P[256][64] = b1 + W1x@x + W1h@h1 ----
        ull acc[8][4];
#pragma unroll
        for (int r = 0; r < 8; r++) {
            ull bb = dup2(sm[S_B1 + g0a + r]);
            acc[r][0] = bb; acc[r][1] = bb; acc[r][2] = bb; acc[r][3] = bb;
        }
#pragma unroll
        for (int i = 0; i < 4; i++) {
            const ull* hv = reinterpret_cast<const ull*>(sm + S_XS + i * 64 + b0);
            ull h0 = hv[0], h1v = hv[1], h2v = hv[2], h3v = hv[3];
            const float* wr = sm + S_W1X + i * 256 + g0a;
#pragma unroll
            for (int r = 0; r < 8; r++) {
                ull w = dup2(wr[r]);
                acc[r][0] = ffma2(w, h0, acc[r][0]);
                acc[r][1] = ffma2(w, h1v, acc[r][1]);
                acc[r][2] = ffma2(w, h2v, acc[r][2]);
                acc[r][3] = ffma2(w, h3v, acc[r][3]);
            }
        }
#pragma unroll 4
        for (int j = 0; j < 64; j++) {
            const ull* hv = reinterpret_cast<const ull*>(sm + S_H1 + j * 64 + b0);
            ull h0 = hv[0], h1v = hv[1], h2v = hv[2], h3v = hv[3];
            const float* wr = sm + S_W1H + j * 256 + g0a;
#pragma unroll
            for (int r = 0; r < 8; r++) {
                ull w = dup2(wr[r]);
                acc[r][0] = ffma2(w, h0, acc[r][0]);
                acc[r][1] = ffma2(w, h1v, acc[r][1]);
                acc[r][2] = ffma2(w, h2v, acc[r][2]);
                acc[r][3] = ffma2(w, h3v, acc[r][3]);
            }
        }
        __syncthreads();

        // ---- enc1 cell update (k = 2gx+a), write h1 in place ----
#pragma unroll
        for (int a = 0; a < 2; a++) {
            const int k = 2 * gx + a;
#pragma unroll
            for (int p = 0; p < 4; p++) {
                float2 pi = unpack2(acc[4 * a + 0][p]);
                float2 pf = unpack2(acc[4 * a + 1][p]);
                float2 pg = unpack2(acc[4 * a + 2][p]);
                float2 po = unpack2(acc[4 * a + 3][p]);
                float2 cc = unpack2(c1[a][p]);
                float hx, hy;
                cell(pi.x, pf.x, pg.x, po.x, cc.x, hx);
                cell(pi.y, pf.y, pg.y, po.y, cc.y, hy);
                c1[a][p] = pack2(cc.x, cc.y);
                reinterpret_cast<ull*>(sm + S_H1 + k * 64 + b0)[p] = pack2(hx, hy);
            }
        }
        __syncthreads();

        // ---- enc2 GEMM: P[128][64] = b2 + W2x@h1 + W2h@h2 ----
        ull a2[4][4];
#pragma unroll
        for (int r = 0; r < 4; r++) {
            ull bb = dup2(sm[S_B2 + g0b + r]);
            a2[r][0] = bb; a2[r][1] = bb; a2[r][2] = bb; a2[r][3] = bb;
        }
#pragma unroll 4
        for (int j = 0; j < 64; j++) {
            const ull* hv = reinterpret_cast<const ull*>(sm + S_H1 + j * 64 + b0);
            ull h0 = hv[0], h1v = hv[1], h2v = hv[2], h3v = hv[3];
            const float* wr = sm + S_W2X + j * 128 + g0b;
#pragma unroll
            for (int r = 0; r < 4; r++) {
                ull w = dup2(wr[r]);
                a2[r][0] = ffma2(w, h0, a2[r][0]);
                a2[r][1] = ffma2(w, h1v, a2[r][1]);
                a2[r][2] = ffma2(w, h2v, a2[r][2]);
                a2[r][3] = ffma2(w, h3v, a2[r][3]);
            }
        }
#pragma unroll 4
        for (int j = 0; j < 32; j++) {
            const ull* hv = reinterpret_cast<const ull*>(sm + S_H2 + j * 64 + b0);
            ull h0 = hv[0], h1v = hv[1], h2v = hv[2], h3v = hv[3];
            const float* wr = sm + S_W2H + j * 128 + g0b;
#pragma unroll
            for (int r = 0; r < 4; r++) {
                ull w = dup2(wr[r]);
                a2[r][0] = ffma2(w, h0, a2[r][0]);
                a2[r][1] = ffma2(w, h1v, a2[r][1]);
                a2[r][2] = ffma2(w, h2v, a2[r][2]);
                a2[r][3] = ffma2(w, h3v, a2[r][3]);
            }
        }
        __syncthreads();

        // ---- enc2 cell update (k = gx), write h2 ----
#pragma unroll
        for (int p = 0; p < 4; p++) {
            float2 pi = unpack2(a2[0][p]);
            float2 pf = unpack2(a2[1][p]);
            float2 pg = unpack2(a2[2][p]);
            float2 po = unpack2(a2[3][p]);
            float2 cc = unpack2(c2[p]);
            float hx, hy;
            cell(pi.x, pf.x, pg.x, po.x, cc.x, hx);
            cell(pi.y, pf.y, pg.y, po.y, cc.y, hy);
            c2[p] = pack2(cc.x, cc.y);
            reinterpret_cast<ull*>(sm + S_H2 + gx * 64 + b0)[p] = pack2(hx, hy);
        }
        __syncthreads();
    }
    // h2 now holds the latent (persistent region, survives weight reload)

    // ---- load decode weights ----
    load_w_perm(d1_Whh, sm + S_WD1H, 64, 64, tid);
    load_w_perm(d1_Wih, sm + S_WD1X, 64, 32, tid);
    load_w_perm(d2_Wih, sm + S_WD2X, 4, 64, tid);
    load_w_perm(d2_Whh, sm + S_WD2H, 4, 4, tid);
    if (tid < 16) {
        int g = tid, gp = 4 * (g % 4) + g / 4;
        sm[S_BD2 + gp] = d2_bih[g] + d2_bhh[g];
    }
    for (int i = tid; i < 4096; i += NT) sm[S_H1 + i] = 0.f;   // hd1 = 0
    for (int i = tid; i < 256; i += NT) sm[S_HD2 + i] = 0.f;   // hd2 = 0
#pragma unroll
    for (int a = 0; a < 2; a++)
#pragma unroll
        for (int p = 0; p < 4; p++) c1[a][p] = 0ull;           // cd1 = 0
    float cd2 = 0.f;
    __syncthreads();

    // ---- XG precompute: XG[g'][b] = bd1 + Wd1x @ latent (constant over t) ----
    {
        ull acc[8][4];
#pragma unroll
        for (int r = 0; r < 8; r++) {
            int gp = g0a + r;
            int k = gp >> 2, ti = gp & 3;
            int g = ti * 64 + k;
            ull bb = dup2(d1_bih[g] + d1_bhh[g]);
            acc[r][0] = bb; acc[r][1] = bb; acc[r][2] = bb; acc[r][3] = bb;
        }
#pragma unroll 4
        for (int j = 0; j < 32; j++) {
            const ull* hv = reinterpret_cast<const ull*>(sm + S_H2 + j * 64 + b0);
            ull h0 = hv[0], h1v = hv[1], h2v = hv[2], h3v = hv[3];
            const float* wr = sm + S_WD1X + j * 256 + g0a;
#pragma unroll
            for (int r = 0; r < 8; r++) {
                ull w = dup2(wr[r]);
                acc[r][0] = ffma2(w, h0, acc[r][0]);
                acc[r][1] = ffma2(w, h1v, acc[r][1]);
                acc[r][2] = ffma2(w, h2v, acc[r][2]);
                acc[r][3] = ffma2(w, h3v, acc[r][3]);
            }
        }
#pragma unroll
        for (int r = 0; r < 8; r++) {
            ull* dst = reinterpret_cast<ull*>(sm + S_XG + (g0a + r) * 64 + b0);
            dst[0] = acc[r][0]; dst[1] = acc[r][1]; dst[2] = acc[r][2]; dst[3] = acc[r][3];
        }
    }
    __syncthreads();

    // =================== DECODE ===================
    for (int t = 0; t < T_; t++) {
        // ---- dec1 GEMM: P = XG + Wd1h @ hd1 ----
        ull acc[8][4];
#pragma unroll
        for (int r = 0; r < 8; r++) {
            const ull* xg = reinterpret_cast<const ull*>(sm + S_XG + (g0a + r) * 64 + b0);
            acc[r][0] = xg[0]; acc[r][1] = xg[1]; acc[r][2] = xg[2]; acc[r][3] = xg[3];
        }
#pragma unroll 4
        for (int j = 0; j < 64; j++) {
            const ull* hv = reinterpret_cast<const ull*>(sm + S_H1 + j * 64 + b0);
            ull h0 = hv[0], h1v = hv[1], h2v = hv[2], h3v = hv[3];
            const float* wr = sm + S_WD1H + j * 256 + g0a;
#pragma unroll
            for (int r = 0; r < 8; r++) {
                ull w = dup2(wr[r]);
                acc[r][0] = ffma2(w, h0, acc[r][0]);
                acc[r][1] = ffma2(w, h1v, acc[r][1]);
                acc[r][2] = ffma2(w, h2v, acc[r][2]);
                acc[r][3] = ffma2(w, h3v, acc[r][3]);
            }
        }
        __syncthreads();

        // ---- dec1 cell update (k = 2gx+a), write hd1 ----
#pragma unroll
        for (int a = 0; a < 2; a++) {
            const int k = 2 * gx + a;
#pragma unroll
            for (int p = 0; p < 4; p++) {
                float2 pi = unpack2(acc[4 * a + 0][p]);
                float2 pf = unpack2(acc[4 * a + 1][p]);
                float2 pg = unpack2(acc[4 * a + 2][p]);
                float2 po = unpack2(acc[4 * a + 3][p]);
                float2 cc = unpack2(c1[a][p]);
                float hx, hy;
                cell(pi.x, pf.x, pg.x, po.x, cc.x, hx);
                cell(pi.y, pf.y, pg.y, po.y, cc.y, hy);
                c1[a][p] = pack2(cc.x, cc.y);
                reinterpret_cast<ull*>(sm + S_H1 + k * 64 + b0)[p] = pack2(hx, hy);
            }
        }
        __syncthreads();

        // ---- dec2 GEMM (16 gates): P2 = bd2 + Wd2x@hd1 + Wd2h@hd2 ----
        if (tid < 128) {
            const int row = tid >> 3;
            const int bb0 = (tid & 7) * 8;
            ull a4[4];
            {
                ull bb = dup2(sm[S_BD2 + row]);
                a4[0] = bb; a4[1] = bb; a4[2] = bb; a4[3] = bb;
            }
#pragma unroll 4
            for (int j = 0; j < 64; j++) {
                const ull* hv = reinterpret_cast<const ull*>(sm + S_H1 + j * 64 + bb0);
                ull w = dup2(sm[S_WD2X + j * 16 + row]);
                a4[0] = ffma2(w, hv[0], a4[0]);
                a4[1] = ffma2(w, hv[1], a4[1]);
                a4[2] = ffma2(w, hv[2], a4[2]);
                a4[3] = ffma2(w, hv[3], a4[3]);
            }
#pragma unroll
            for (int j = 0; j < 4; j++) {
                const ull* hv = reinterpret_cast<const ull*>(sm + S_HD2 + j * 64 + bb0);
                ull w = dup2(sm[S_WD2H + j * 16 + row]);
                a4[0] = ffma2(w, hv[0], a4[0]);
                a4[1] = ffma2(w, hv[1], a4[1]);
                a4[2] = ffma2(w, hv[2], a4[2]);
                a4[3] = ffma2(w, hv[3], a4[3]);
            }
            ull* ps = reinterpret_cast<ull*>(sm + S_P2 + row * 64 + bb0);
            ps[0] = a4[0]; ps[1] = a4[1]; ps[2] = a4[2]; ps[3] = a4[3];
        }
        __syncthreads();

        // ---- dec2 cell update + output write: thread owns (k = tid>>6, b = tid&63) ----
        {
            const int k = tid >> 6;
            const int b = tid & 63;
            float pi = sm[S_P2 + (4 * k + 0) * 64 + b];
            float pf = sm[S_P2 + (4 * k + 1) * 64 + b];
            float pg = sm[S_P2 + (4 * k + 2) * 64 + b];
            float po = sm[S_P2 + (4 * k + 3) * 64 + b];
            float h;
            cell(pi, pf, pg, po, cd2, h);
            sm[S_HD2 + k * 64 + b] = h;
            out[(base + b) * (T_ * 4) + t * 4 + k] = h;
        }
        __syncthreads();
    }
}

extern "C" void kernel_launch(void* const* d_in, const int* in_sizes, int n_in,
                              void* d_out, int out_size) {
    cudaFuncSetAttribute(lstm_ae_kernel,
                         cudaFuncAttributeMaxDynamicSharedMemorySize, SMEM_BYTES);
    lstm_ae_kernel<<<NBLK, NT, SMEM_BYTES>>>(
        (const float*)d_in[0],
        (const float*)d_in[1], (const float*)d_in[2], (const float*)d_in[3], (const float*)d_in[4],
        (const float*)d_in[5], (const float*)d_in[6], (const float*)d_in[7], (const float*)d_in[8],
        (const float*)d_in[9], (const float*)d_in[10], (const float*)d_in[11], (const float*)d_in[12],
        (const float*)d_in[13], (const float*)d_in[14], (const float*)d_in[15], (const float*)d_in[16],
        (float*)d_out);
}